// round 10
// baseline (speedup 1.0000x reference)
#include <cuda_runtime.h>
#include <cuda_fp16.h>
#include <math.h>
#include <stdint.h>

#define N_NODES 50000
#define N_EDGES 800000
#define NB      250
#define NT      8
#define C_IN    32
#define C_OUT   64
#define NPG     200   // nodes per graph (contiguous)
#define M_ALL   (NT * N_NODES)       // 400000 rows = n*8+t
#define SCAN_NBLK ((N_NODES + 255) / 256)   // 196

// ---------------- scratch (static device globals; no allocation) -------------
__device__ __half g_xh[(size_t)N_NODES * NT * C_IN];    // [n][t][c] fp16 (row 512B)
__device__ __half g_hA[(size_t)N_NODES * NT * C_OUT];   // ping
__device__ __half g_hB[(size_t)N_NODES * NT * C_OUT];   // pong
__device__ __half g_W1h[C_IN * C_OUT];
__device__ __half g_W2h[C_OUT * C_OUT];
__device__ __half g_W3h[C_OUT * C_OUT];
__device__ int    g_deg[N_NODES];
__device__ int    g_cnt[N_NODES];
__device__ int    g_rowptr[N_NODES + 1];
__device__ int    g_bsum[SCAN_NBLK];
__device__ float  g_dinv[N_NODES];
__device__ int    g_src[N_EDGES];
__device__ float  g_norm[N_EDGES];

// ---------------- fused setup: zero deg/cnt + convert W + transpose x --------
__global__ void setup_a_kernel(const float* __restrict__ x,
                               const float* __restrict__ W1,
                               const float* __restrict__ W2,
                               const float* __restrict__ W3) {
    int i = blockIdx.x * blockDim.x + threadIdx.x;
    if (i < N_NODES) { g_deg[i] = 0; g_cnt[i] = 0; }
    if (i < C_OUT * C_OUT) { g_W2h[i] = __float2half_rn(W2[i]);
                             g_W3h[i] = __float2half_rn(W3[i]); }
    if (i < C_IN * C_OUT)  g_W1h[i] = __float2half_rn(W1[i]);
    if (i >= N_NODES * C_IN) return;
    // transpose: x[N, C_IN, T] -> g_xh [n][t][c]
    int n = i / C_IN, c = i % C_IN;
    const float4* p = (const float4*)(x + (size_t)i * NT);
    float4 a = p[0], b4 = p[1];
    float v[8] = {a.x, a.y, a.z, a.w, b4.x, b4.y, b4.z, b4.w};
#pragma unroll
    for (int t = 0; t < NT; t++)
        g_xh[(size_t)n * (NT * C_IN) + t * C_IN + c] = __float2half_rn(v[t]);
}

__global__ void count_deg_kernel(const int* __restrict__ ei) {
    int e = blockIdx.x * blockDim.x + threadIdx.x;
    if (e >= N_EDGES) return;
    int dst = ei[N_EDGES + e];
    if ((unsigned)dst < (unsigned)N_NODES)
        atomicAdd(&g_deg[dst], 1);
}

// ---------------- parallel scan: part (per-block) + finish -------------------
__global__ void __launch_bounds__(256) scan_part_kernel() {
    __shared__ int ws[8];
    int b = blockIdx.x, tid = threadIdx.x;
    int i = b * 256 + tid;
    int lane = tid & 31, wid = tid >> 5;
    int v = (i < N_NODES) ? g_deg[i] : 0;
    if (i < N_NODES) g_dinv[i] = rsqrtf((float)(v + 1));  // +1 self loop
    int x = v;
#pragma unroll
    for (int off = 1; off < 32; off <<= 1) {
        int y = __shfl_up_sync(0xffffffffu, x, off);
        if (lane >= off) x += y;
    }
    if (lane == 31) ws[wid] = x;
    __syncthreads();
    if (tid < 8) {
        int s = ws[tid];
#pragma unroll
        for (int off = 1; off < 8; off <<= 1) {
            int y = __shfl_up_sync(0x000000ffu, s, off);
            if (tid >= off) s += y;
        }
        ws[tid] = s;
    }
    __syncthreads();
    int woff = wid ? ws[wid - 1] : 0;
    if (i < N_NODES) g_rowptr[i] = woff + x - v;   // local exclusive
    if (tid == 0) g_bsum[b] = ws[7];
}

__global__ void __launch_bounds__(1024) scan_finish_kernel() {
    __shared__ int boff[SCAN_NBLK];
    int tid = threadIdx.x;
    if (tid == 0) {
        int run = 0;
        for (int b = 0; b < SCAN_NBLK; b++) { int s = g_bsum[b]; boff[b] = run; run += s; }
        g_rowptr[N_NODES] = run;
    }
    __syncthreads();
    for (int i = tid; i < N_NODES; i += 1024)
        g_rowptr[i] += boff[i >> 8];
}

__global__ void fill_csr_kernel(const int* __restrict__ ei) {
    int e = blockIdx.x * blockDim.x + threadIdx.x;
    if (e >= N_EDGES) return;
    int src = ei[e];
    int dst = ei[N_EDGES + e];
    if ((unsigned)src >= (unsigned)N_NODES ||
        (unsigned)dst >= (unsigned)N_NODES) return;
    int pos = g_rowptr[dst] + atomicAdd(&g_cnt[dst], 1);
    g_src[pos]  = src;
    g_norm[pos] = g_dinv[src] * g_dinv[dst];
}

// ---------------- helpers ----------------------------------------------------
__device__ __forceinline__ float2 u2f(uint32_t u) {
    __half2 h = *(__half2*)&u;
    return __half22float2(h);
}
__device__ __forceinline__ uint32_t f2u(float a, float b) {
    __half2 h = __floats2half2_rn(a, b);
    return *(uint32_t*)&h;
}
__device__ __forceinline__ uint32_t pack_h2(__half a, __half b) {
    __half2 h = __halves2half2(a, b);
    return *(uint32_t*)&h;
}

// ---------------- fused aggregation + HMMA GEMM ------------------------------
// Block = 16 nodes (128 GEMM rows r=n*8+t) x 64 cols, 256 threads (8 warps).
// in and out MUST be distinct buffers (cross-block neighbor reads of `in`).
template <int K>
__global__ void __launch_bounds__(256) fused_agg_gemm_kernel(
    const uint4* __restrict__ in, const __half* __restrict__ Wh,
    const float* __restrict__ bias, __half* __restrict__ out) {
    constexpr int NU  = K / 32;          // uint4 per lane per row
    constexpr int C2  = K / 2;           // half2 per (n,t) GEMM row
    constexpr int PAD = C2 + ((K == 64) ? 4 : 2);
    constexpr int KS  = K / 16;
    __shared__ uint32_t As[128 * PAD];

    int tid = threadIdx.x, lane = tid & 31, warp = tid >> 5;
    int nb = blockIdx.x * 16;
    int wm = warp >> 1, wn = warp & 1;
    int col0 = wn * 32;
    int lq = lane >> 2, lr = lane & 3;

    // B fragments preload (gmem, tiny, L2-hot)
    uint32_t breg[KS][4][2];
#pragma unroll
    for (int ks = 0; ks < KS; ks++)
#pragma unroll
        for (int j = 0; j < 4; j++) {
            int n  = col0 + j * 8 + lq;
            int kb = ks * 16 + lr * 2;
            breg[ks][j][0] = pack_h2(Wh[kb * 64 + n],       Wh[(kb + 1) * 64 + n]);
            breg[ks][j][1] = pack_h2(Wh[(kb + 8) * 64 + n], Wh[(kb + 9) * 64 + n]);
        }

    // ---- phase 1: aggregate 2 nodes per warp into smem tile ----
    for (int rep = 0; rep < 2; rep++) {
        int n = nb + warp * 2 + rep;
        float dv = g_dinv[n];
        float dv2 = dv * dv;
        float2 acc[NU * 4];
#pragma unroll
        for (int u = 0; u < NU; u++) {
            uint4 v = __ldg(&in[(size_t)n * K + u * 32 + lane]);
            uint32_t uu[4] = {v.x, v.y, v.z, v.w};
#pragma unroll
            for (int j = 0; j < 4; j++) {
                float2 f = u2f(uu[j]);
                acc[u * 4 + j].x = dv2 * f.x;
                acc[u * 4 + j].y = dv2 * f.y;
            }
        }
        int s = g_rowptr[n], e2 = g_rowptr[n + 1];
        for (int base = s; base < e2; base += 32) {
            int idx = base + lane;
            int sl = 0; float nl = 0.f;
            if (idx < e2) { sl = g_src[idx]; nl = g_norm[idx]; }
            int cnt = min(32, e2 - base);
            for (int j = 0; j < cnt; j++) {
                int src  = __shfl_sync(0xffffffffu, sl, j);
                float wt = __shfl_sync(0xffffffffu, nl, j);
#pragma unroll
                for (int u = 0; u < NU; u++) {
                    uint4 v = __ldg(&in[(size_t)src * K + u * 32 + lane]);
                    uint32_t uu[4] = {v.x, v.y, v.z, v.w};
#pragma unroll
                    for (int q = 0; q < 4; q++) {
                        float2 f = u2f(uu[q]);
                        acc[u * 4 + q].x = fmaf(wt, f.x, acc[u * 4 + q].x);
                        acc[u * 4 + q].y = fmaf(wt, f.y, acc[u * 4 + q].y);
                    }
                }
            }
        }
        // write fp16 tile rows: flat half2 f -> t = f/C2, c2 = f%C2
        int ln = warp * 2 + rep;
#pragma unroll
        for (int u = 0; u < NU; u++)
#pragma unroll
            for (int j = 0; j < 4; j++) {
                int f = (u * 32 + lane) * 4 + j;
                int t = f / C2, c2 = f % C2;   // compile-time shifts
                As[(ln * 8 + t) * PAD + c2] = f2u(acc[u * 4 + j].x, acc[u * 4 + j].y);
            }
    }
    __syncthreads();

    // ---- phase 2: 128x64 HMMA tile GEMM from smem ----
    float acc2[2][4][4];
#pragma unroll
    for (int mt = 0; mt < 2; mt++)
#pragma unroll
        for (int j = 0; j < 4; j++)
#pragma unroll
            for (int q = 0; q < 4; q++) acc2[mt][j][q] = 0.f;

    int rbase = wm * 32;
#pragma unroll
    for (int mt = 0; mt < 2; mt++) {
#pragma unroll
        for (int ks = 0; ks < KS; ks++) {
            int c2a = ks * 8 + lr;
            uint32_t a0 = As[(rbase + mt * 16 + lq) * PAD + c2a];
            uint32_t a1 = As[(rbase + mt * 16 + lq + 8) * PAD + c2a];
            uint32_t a2 = As[(rbase + mt * 16 + lq) * PAD + c2a + 4];
            uint32_t a3 = As[(rbase + mt * 16 + lq + 8) * PAD + c2a + 4];
#pragma unroll
            for (int j = 0; j < 4; j++) {
                asm volatile(
                    "mma.sync.aligned.m16n8k16.row.col.f32.f16.f16.f32 "
                    "{%0,%1,%2,%3}, {%4,%5,%6,%7}, {%8,%9}, {%0,%1,%2,%3};"
                    : "+f"(acc2[mt][j][0]), "+f"(acc2[mt][j][1]),
                      "+f"(acc2[mt][j][2]), "+f"(acc2[mt][j][3])
                    : "r"(a0), "r"(a1), "r"(a2), "r"(a3),
                      "r"(breg[ks][j][0]), "r"(breg[ks][j][1]));
            }
        }
    }

    // epilogue: bias + relu, fp16 store
    size_t row0 = (size_t)blockIdx.x * 128 + wm * 32;
#pragma unroll
    for (int mt = 0; mt < 2; mt++) {
#pragma unroll
        for (int j = 0; j < 4; j++) {
            int c = col0 + j * 8 + lr * 2;
            float bx = bias[c], by = bias[c + 1];
            size_t r0 = row0 + mt * 16 + lq;
            float ox = fmaxf(acc2[mt][j][0] + bx, 0.f);
            float oy = fmaxf(acc2[mt][j][1] + by, 0.f);
            *(__half2*)(out + r0 * 64 + c) = __floats2half2_rn(ox, oy);
            float oz = fmaxf(acc2[mt][j][2] + bx, 0.f);
            float ow = fmaxf(acc2[mt][j][3] + by, 0.f);
            *(__half2*)(out + (r0 + 8) * 64 + c) = __floats2half2_rn(oz, ow);
        }
    }
}

// ---------------- pooling: out[b, c, t] (max) and [b, 64+c, t] (mean) --------
template <bool FIRST>
__global__ void __launch_bounds__(256) pool_all_kernel(const __half* __restrict__ h,
                                                       float* __restrict__ out) {
    int b = blockIdx.x, t = blockIdx.y;
    int tid = threadIdx.x;
    int c = tid & 63, g = tid >> 6;  // 4 groups
    const __half* hp = h + ((size_t)b * NPG * 8 + t) * 64 + c;
    float mx = -1e30f, sm = 0.f;
    for (int i = g; i < NPG; i += 4) {
        float v = __half2float(hp[(size_t)i * 512]);
        mx = fmaxf(mx, v);
        sm += v;
    }
    __shared__ float smx[4][64], ssm[4][64];
    smx[g][c] = mx; ssm[g][c] = sm;
    __syncthreads();
    if (tid < 64) {
        float m = fmaxf(fmaxf(smx[0][tid], smx[1][tid]),
                        fmaxf(smx[2][tid], smx[3][tid]));
        float s = (ssm[0][tid] + ssm[1][tid] + ssm[2][tid] + ssm[3][tid])
                  * (1.f / (float)NPG);
        if (FIRST) {
            out[b * 1024 + tid * 8 + t]        = m;
            out[b * 1024 + (64 + tid) * 8 + t] = s;
        } else {
            out[b * 1024 + tid * 8 + t]        += m;
            out[b * 1024 + (64 + tid) * 8 + t] += s;
        }
    }
}

// ---------------- launch -----------------------------------------------------
extern "C" void kernel_launch(void* const* d_in, const int* in_sizes, int n_in,
                              void* d_out, int out_size) {
    const float* x  = (const float*)d_in[0];
    const int*   ei = (const int*)d_in[1];     // int32 [2, E]
    const float* W1 = (const float*)d_in[3];
    const float* b1 = (const float*)d_in[4];
    const float* W2 = (const float*)d_in[5];
    const float* b2 = (const float*)d_in[6];
    const float* W3 = (const float*)d_in[7];
    const float* b3 = (const float*)d_in[8];
    float* out = (float*)d_out;

    __half *xh, *hA, *hB, *w1h, *w2h, *w3h;
    cudaGetSymbolAddress((void**)&xh,  g_xh);
    cudaGetSymbolAddress((void**)&hA,  g_hA);
    cudaGetSymbolAddress((void**)&hB,  g_hB);
    cudaGetSymbolAddress((void**)&w1h, g_W1h);
    cudaGetSymbolAddress((void**)&w2h, g_W2h);
    cudaGetSymbolAddress((void**)&w3h, g_W3h);

    // setup: 5 launches -> ncu -s 5 profiles fused<32> (launch index 5)
    setup_a_kernel<<<(N_NODES * C_IN + 255) / 256, 256>>>(x, W1, W2, W3);
    count_deg_kernel<<<(N_EDGES + 255) / 256, 256>>>(ei);
    scan_part_kernel<<<SCAN_NBLK, 256>>>();
    scan_finish_kernel<<<1, 1024>>>();
    fill_csr_kernel<<<(N_EDGES + 255) / 256, 256>>>(ei);

    const int FUSE_GRID = N_NODES / 16;   // 3125 blocks, 16 nodes each
    dim3 pool_grid(NB, NT);

    // layer 1: xh -> hA
    fused_agg_gemm_kernel<32><<<FUSE_GRID, 256>>>((const uint4*)xh, w1h, b1, hA);
    pool_all_kernel<true><<<pool_grid, 256>>>(hA, out);
    // layer 2: hA -> hB  (distinct buffers: neighbor reads must see layer-1 h)
    fused_agg_gemm_kernel<64><<<FUSE_GRID, 256>>>((const uint4*)hA, w2h, b2, hB);
    pool_all_kernel<false><<<pool_grid, 256>>>(hB, out);
    // layer 3: hB -> hA
    fused_agg_gemm_kernel<64><<<FUSE_GRID, 256>>>((const uint4*)hB, w3h, b3, hA);
    pool_all_kernel<false><<<pool_grid, 256>>>(hA, out);
}

// round 12
// speedup vs baseline: 1.5576x; 1.5576x over previous
#include <cuda_runtime.h>
#include <cuda_fp16.h>
#include <math.h>
#include <stdint.h>

#define N_NODES 50000
#define N_EDGES 800000
#define NB      250
#define NT      8
#define C_IN    32
#define C_OUT   64
#define NPG     200   // nodes per graph (contiguous)
#define M_ALL   (NT * N_NODES)       // 400000 rows = n*8+t
#define SCAN_NBLK ((N_NODES + 255) / 256)   // 196

// ---------------- scratch (static device globals; no allocation) -------------
__device__ __half g_xh[(size_t)N_NODES * NT * C_IN];    // [n][t][c] fp16 (row 512B)
__device__ __half g_h[(size_t)N_NODES * NT * C_OUT];    // activations
__device__ __half g_agg[(size_t)N_NODES * NT * C_OUT];  // aggregation output
__device__ __half g_W1h[C_IN * C_OUT];
__device__ __half g_W2h[C_OUT * C_OUT];
__device__ __half g_W3h[C_OUT * C_OUT];
__device__ int    g_deg[N_NODES];
__device__ int    g_cnt[N_NODES];
__device__ int    g_rowptr[N_NODES + 1];
__device__ int    g_bsum[SCAN_NBLK];
__device__ float  g_dinv[N_NODES];
__device__ int    g_src[N_EDGES];
__device__ float  g_norm[N_EDGES];

// ---------------- fused setup: zero deg/cnt + convert W + transpose x --------
__global__ void setup_a_kernel(const float* __restrict__ x,
                               const float* __restrict__ W1,
                               const float* __restrict__ W2,
                               const float* __restrict__ W3) {
    int i = blockIdx.x * blockDim.x + threadIdx.x;
    if (i < N_NODES) { g_deg[i] = 0; g_cnt[i] = 0; }
    if (i < C_OUT * C_OUT) { g_W2h[i] = __float2half_rn(W2[i]);
                             g_W3h[i] = __float2half_rn(W3[i]); }
    if (i < C_IN * C_OUT)  g_W1h[i] = __float2half_rn(W1[i]);
    if (i >= N_NODES * C_IN) return;
    // transpose: x[N, C_IN, T] -> g_xh [n][t][c]
    int n = i / C_IN, c = i % C_IN;
    const float4* p = (const float4*)(x + (size_t)i * NT);
    float4 a = p[0], b4 = p[1];
    float v[8] = {a.x, a.y, a.z, a.w, b4.x, b4.y, b4.z, b4.w};
#pragma unroll
    for (int t = 0; t < NT; t++)
        g_xh[(size_t)n * (NT * C_IN) + t * C_IN + c] = __float2half_rn(v[t]);
}

__global__ void count_deg_kernel(const int* __restrict__ ei) {
    int e = blockIdx.x * blockDim.x + threadIdx.x;
    if (e >= N_EDGES) return;
    int dst = ei[N_EDGES + e];
    if ((unsigned)dst < (unsigned)N_NODES)
        atomicAdd(&g_deg[dst], 1);
}

// ---------------- parallel scan: part (per-block) + finish -------------------
__global__ void __launch_bounds__(256) scan_part_kernel() {
    __shared__ int ws[8];
    int b = blockIdx.x, tid = threadIdx.x;
    int i = b * 256 + tid;
    int lane = tid & 31, wid = tid >> 5;
    int v = (i < N_NODES) ? g_deg[i] : 0;
    if (i < N_NODES) g_dinv[i] = rsqrtf((float)(v + 1));  // +1 self loop
    int x = v;
#pragma unroll
    for (int off = 1; off < 32; off <<= 1) {
        int y = __shfl_up_sync(0xffffffffu, x, off);
        if (lane >= off) x += y;
    }
    if (lane == 31) ws[wid] = x;
    __syncthreads();
    if (tid < 8) {
        int s = ws[tid];
#pragma unroll
        for (int off = 1; off < 8; off <<= 1) {
            int y = __shfl_up_sync(0x000000ffu, s, off);
            if (tid >= off) s += y;
        }
        ws[tid] = s;
    }
    __syncthreads();
    int woff = wid ? ws[wid - 1] : 0;
    if (i < N_NODES) g_rowptr[i] = woff + x - v;   // local exclusive
    if (tid == 0) g_bsum[b] = ws[7];
}

// single block, 1024 threads: parallel scan of 196 block sums, then apply.
// NOTE: cross-warp smem producer->consumer edges need __syncthreads (R11 bug).
__global__ void __launch_bounds__(1024) scan_finish_kernel() {
    __shared__ int boff[256];   // exclusive prefix of bsum
    __shared__ int wsum[8];
    int tid = threadIdx.x;
    int lane = tid & 31, wid = tid >> 5;
    int v = 0, x = 0;
    if (tid < 256) {
        v = (tid < SCAN_NBLK) ? g_bsum[tid] : 0;
        x = v;
#pragma unroll
        for (int off = 1; off < 32; off <<= 1) {
            int y = __shfl_up_sync(0xffffffffu, x, off);
            if (lane >= off) x += y;
        }
        if (lane == 31) wsum[wid] = x;
    }
    __syncthreads();                       // all wsum writes visible
    if (tid == 0) {
        int run = 0;
#pragma unroll
        for (int w = 0; w < 8; w++) { int s = wsum[w]; wsum[w] = run; run += s; }
        g_rowptr[N_NODES] = run;
    }
    __syncthreads();                       // exclusive wsum visible
    if (tid < 256)
        boff[tid] = wsum[wid] + x - v;     // x,v kept in registers
    __syncthreads();
    for (int i = tid; i < N_NODES; i += 1024)
        g_rowptr[i] += boff[i >> 8];
}

__global__ void fill_csr_kernel(const int* __restrict__ ei) {
    int e = blockIdx.x * blockDim.x + threadIdx.x;
    if (e >= N_EDGES) return;
    int src = ei[e];
    int dst = ei[N_EDGES + e];
    if ((unsigned)src >= (unsigned)N_NODES ||
        (unsigned)dst >= (unsigned)N_NODES) return;
    int pos = g_rowptr[dst] + atomicAdd(&g_cnt[dst], 1);
    if ((unsigned)pos < (unsigned)N_EDGES) {   // belt-and-braces
        g_src[pos]  = src;
        g_norm[pos] = g_dinv[src] * g_dinv[dst];
    }
}

// ---------------- helpers ----------------------------------------------------
__device__ __forceinline__ float2 u2f(uint32_t u) {
    __half2 h = *(__half2*)&u;
    return __half22float2(h);
}
__device__ __forceinline__ uint32_t f2u(float a, float b) {
    __half2 h = __floats2half2_rn(a, b);
    return *(uint32_t*)&h;
}
__device__ __forceinline__ uint32_t pack_h2(__half a, __half b) {
    __half2 h = __halves2half2(a, b);
    return *(uint32_t*)&h;
}

// ---------------- aggregation: warp per node, edge-unrolled ------------------
// agg32: row = 512B = 32 uint4; lane owns one uint4 (8 float acc). 4-edge unroll.
__global__ void __launch_bounds__(256) agg32_all_kernel(uint4* __restrict__ out) {
    int w = (blockIdx.x * blockDim.x + threadIdx.x) >> 5;
    int lane = threadIdx.x & 31;
    if (w >= N_NODES) return;
    const uint4* X4 = (const uint4*)g_xh;
    float dv = g_dinv[w];
    float dv2 = dv * dv;
    float2 acc[4];
    {
        uint4 v = __ldg(&X4[(size_t)w * 32 + lane]);
        uint32_t uu[4] = {v.x, v.y, v.z, v.w};
#pragma unroll
        for (int q = 0; q < 4; q++) {
            float2 f = u2f(uu[q]);
            acc[q].x = dv2 * f.x; acc[q].y = dv2 * f.y;
        }
    }
    int s = g_rowptr[w], e2 = g_rowptr[w + 1];
    for (int base = s; base < e2; base += 32) {
        int idx = base + lane;
        int sl = 0; float nl = 0.f;
        if (idx < e2) { sl = g_src[idx]; nl = g_norm[idx]; }
        int cnt = min(32, e2 - base);
        int j = 0;
        for (; j + 4 <= cnt; j += 4) {
            int s0 = __shfl_sync(0xffffffffu, sl, j);
            int s1 = __shfl_sync(0xffffffffu, sl, j + 1);
            int s2 = __shfl_sync(0xffffffffu, sl, j + 2);
            int s3 = __shfl_sync(0xffffffffu, sl, j + 3);
            float w0 = __shfl_sync(0xffffffffu, nl, j);
            float w1 = __shfl_sync(0xffffffffu, nl, j + 1);
            float w2 = __shfl_sync(0xffffffffu, nl, j + 2);
            float w3 = __shfl_sync(0xffffffffu, nl, j + 3);
            uint4 v0 = __ldg(&X4[(size_t)s0 * 32 + lane]);
            uint4 v1 = __ldg(&X4[(size_t)s1 * 32 + lane]);
            uint4 v2 = __ldg(&X4[(size_t)s2 * 32 + lane]);
            uint4 v3 = __ldg(&X4[(size_t)s3 * 32 + lane]);
            uint32_t u0[4] = {v0.x, v0.y, v0.z, v0.w};
            uint32_t u1[4] = {v1.x, v1.y, v1.z, v1.w};
            uint32_t u2[4] = {v2.x, v2.y, v2.z, v2.w};
            uint32_t u3[4] = {v3.x, v3.y, v3.z, v3.w};
#pragma unroll
            for (int q = 0; q < 4; q++) {
                float2 f0 = u2f(u0[q]), f1 = u2f(u1[q]);
                float2 f2 = u2f(u2[q]), f3 = u2f(u3[q]);
                acc[q].x = fmaf(w0, f0.x, acc[q].x); acc[q].y = fmaf(w0, f0.y, acc[q].y);
                acc[q].x = fmaf(w1, f1.x, acc[q].x); acc[q].y = fmaf(w1, f1.y, acc[q].y);
                acc[q].x = fmaf(w2, f2.x, acc[q].x); acc[q].y = fmaf(w2, f2.y, acc[q].y);
                acc[q].x = fmaf(w3, f3.x, acc[q].x); acc[q].y = fmaf(w3, f3.y, acc[q].y);
            }
        }
        for (; j < cnt; j++) {
            int src  = __shfl_sync(0xffffffffu, sl, j);
            float wt = __shfl_sync(0xffffffffu, nl, j);
            uint4 v = __ldg(&X4[(size_t)src * 32 + lane]);
            uint32_t uu[4] = {v.x, v.y, v.z, v.w};
#pragma unroll
            for (int q = 0; q < 4; q++) {
                float2 f = u2f(uu[q]);
                acc[q].x = fmaf(wt, f.x, acc[q].x);
                acc[q].y = fmaf(wt, f.y, acc[q].y);
            }
        }
    }
    uint4 o;
    o.x = f2u(acc[0].x, acc[0].y); o.y = f2u(acc[1].x, acc[1].y);
    o.z = f2u(acc[2].x, acc[2].y); o.w = f2u(acc[3].x, acc[3].y);
    out[(size_t)w * 32 + lane] = o;
}

// agg64: row = 1024B = 64 uint4; lane owns two uint4 (16 float acc). 2-edge unroll.
__global__ void __launch_bounds__(256) agg64_all_kernel(const uint4* __restrict__ in,
                                                        uint4* __restrict__ out) {
    int w = (blockIdx.x * blockDim.x + threadIdx.x) >> 5;
    int lane = threadIdx.x & 31;
    if (w >= N_NODES) return;
    float dv = g_dinv[w];
    float dv2 = dv * dv;
    float2 acc[8];
    {
        uint4 v0 = __ldg(&in[(size_t)w * 64 + lane]);
        uint4 v1 = __ldg(&in[(size_t)w * 64 + 32 + lane]);
        uint32_t u[8] = {v0.x, v0.y, v0.z, v0.w, v1.x, v1.y, v1.z, v1.w};
#pragma unroll
        for (int k = 0; k < 8; k++) {
            float2 f = u2f(u[k]);
            acc[k].x = dv2 * f.x; acc[k].y = dv2 * f.y;
        }
    }
    int s = g_rowptr[w], e2 = g_rowptr[w + 1];
    for (int base = s; base < e2; base += 32) {
        int idx = base + lane;
        int sl = 0; float nl = 0.f;
        if (idx < e2) { sl = g_src[idx]; nl = g_norm[idx]; }
        int cnt = min(32, e2 - base);
        int j = 0;
        for (; j + 2 <= cnt; j += 2) {
            int s0 = __shfl_sync(0xffffffffu, sl, j);
            int s1 = __shfl_sync(0xffffffffu, sl, j + 1);
            float w0 = __shfl_sync(0xffffffffu, nl, j);
            float w1 = __shfl_sync(0xffffffffu, nl, j + 1);
            uint4 a0 = __ldg(&in[(size_t)s0 * 64 + lane]);
            uint4 a1 = __ldg(&in[(size_t)s0 * 64 + 32 + lane]);
            uint4 b0 = __ldg(&in[(size_t)s1 * 64 + lane]);
            uint4 b1 = __ldg(&in[(size_t)s1 * 64 + 32 + lane]);
            uint32_t ua[8] = {a0.x, a0.y, a0.z, a0.w, a1.x, a1.y, a1.z, a1.w};
            uint32_t ub[8] = {b0.x, b0.y, b0.z, b0.w, b1.x, b1.y, b1.z, b1.w};
#pragma unroll
            for (int k = 0; k < 8; k++) {
                float2 fa = u2f(ua[k]), fb = u2f(ub[k]);
                acc[k].x = fmaf(w0, fa.x, acc[k].x); acc[k].y = fmaf(w0, fa.y, acc[k].y);
                acc[k].x = fmaf(w1, fb.x, acc[k].x); acc[k].y = fmaf(w1, fb.y, acc[k].y);
            }
        }
        for (; j < cnt; j++) {
            int src  = __shfl_sync(0xffffffffu, sl, j);
            float wt = __shfl_sync(0xffffffffu, nl, j);
            uint4 v0 = __ldg(&in[(size_t)src * 64 + lane]);
            uint4 v1 = __ldg(&in[(size_t)src * 64 + 32 + lane]);
            uint32_t u[8] = {v0.x, v0.y, v0.z, v0.w, v1.x, v1.y, v1.z, v1.w};
#pragma unroll
            for (int k = 0; k < 8; k++) {
                float2 f = u2f(u[k]);
                acc[k].x = fmaf(wt, f.x, acc[k].x);
                acc[k].y = fmaf(wt, f.y, acc[k].y);
            }
        }
    }
    uint4 o0, o1;
    o0.x = f2u(acc[0].x, acc[0].y); o0.y = f2u(acc[1].x, acc[1].y);
    o0.z = f2u(acc[2].x, acc[2].y); o0.w = f2u(acc[3].x, acc[3].y);
    o1.x = f2u(acc[4].x, acc[4].y); o1.y = f2u(acc[5].x, acc[5].y);
    o1.z = f2u(acc[6].x, acc[6].y); o1.w = f2u(acc[7].x, acc[7].y);
    out[(size_t)w * 64 + lane] = o0;
    out[(size_t)w * 64 + 32 + lane] = o1;
}

// ---------------- HMMA GEMM: out = relu(A[M,K]h @ W[K,64]h + b) fp16 out -----
// Rows are flat r = n*8+t (layout [n][t][c]). Block = 128 rows x 64 cols.
template <int K>
__global__ void __launch_bounds__(256) hgemm_bias_relu_kernel(
    const __half* __restrict__ A, const __half* __restrict__ Wh,
    const float* __restrict__ bias, __half* __restrict__ out) {
    constexpr int KS = K / 16;
    int tid = threadIdx.x, lane = tid & 31, warp = tid >> 5;
    int wm = warp >> 1, wn = warp & 1;
    size_t row0 = (size_t)blockIdx.x * 128 + wm * 32;
    int col0 = wn * 32;
    int lq = lane >> 2, lr = lane & 3;

    // preload B fragments
    uint32_t breg[KS][4][2];
#pragma unroll
    for (int ks = 0; ks < KS; ks++)
#pragma unroll
        for (int j = 0; j < 4; j++) {
            int n  = col0 + j * 8 + lq;
            int kb = ks * 16 + lr * 2;
            breg[ks][j][0] = pack_h2(Wh[kb * 64 + n],       Wh[(kb + 1) * 64 + n]);
            breg[ks][j][1] = pack_h2(Wh[(kb + 8) * 64 + n], Wh[(kb + 9) * 64 + n]);
        }

    float acc[2][4][4];
#pragma unroll
    for (int mt = 0; mt < 2; mt++)
#pragma unroll
        for (int j = 0; j < 4; j++)
#pragma unroll
            for (int q = 0; q < 4; q++) acc[mt][j][q] = 0.f;

#pragma unroll
    for (int mt = 0; mt < 2; mt++) {
        const __half* Ab = A + (row0 + mt * 16) * K;
#pragma unroll
        for (int ks = 0; ks < KS; ks++) {
            int kc = ks * 16 + lr * 2;
            uint32_t a0 = *(const uint32_t*)(Ab + (size_t)lq * K + kc);
            uint32_t a1 = *(const uint32_t*)(Ab + (size_t)(lq + 8) * K + kc);
            uint32_t a2 = *(const uint32_t*)(Ab + (size_t)lq * K + kc + 8);
            uint32_t a3 = *(const uint32_t*)(Ab + (size_t)(lq + 8) * K + kc + 8);
#pragma unroll
            for (int j = 0; j < 4; j++) {
                asm volatile(
                    "mma.sync.aligned.m16n8k16.row.col.f32.f16.f16.f32 "
                    "{%0,%1,%2,%3}, {%4,%5,%6,%7}, {%8,%9}, {%0,%1,%2,%3};"
                    : "+f"(acc[mt][j][0]), "+f"(acc[mt][j][1]),
                      "+f"(acc[mt][j][2]), "+f"(acc[mt][j][3])
                    : "r"(a0), "r"(a1), "r"(a2), "r"(a3),
                      "r"(breg[ks][j][0]), "r"(breg[ks][j][1]));
            }
        }
    }

    // epilogue: bias + relu, fp16 store
#pragma unroll
    for (int mt = 0; mt < 2; mt++) {
#pragma unroll
        for (int j = 0; j < 4; j++) {
            int c = col0 + j * 8 + lr * 2;
            float bx = bias[c], by = bias[c + 1];
            size_t r0 = row0 + mt * 16 + lq;
            float ox = fmaxf(acc[mt][j][0] + bx, 0.f);
            float oy = fmaxf(acc[mt][j][1] + by, 0.f);
            *(__half2*)(out + r0 * 64 + c) = __floats2half2_rn(ox, oy);
            float oz = fmaxf(acc[mt][j][2] + bx, 0.f);
            float ow = fmaxf(acc[mt][j][3] + by, 0.f);
            *(__half2*)(out + (r0 + 8) * 64 + c) = __floats2half2_rn(oz, ow);
        }
    }
}

// ---------------- pooling: out[b, c, t] (max) and [b, 64+c, t] (mean) --------
template <bool FIRST>
__global__ void __launch_bounds__(256) pool_all_kernel(const __half* __restrict__ h,
                                                       float* __restrict__ out) {
    int b = blockIdx.x, t = blockIdx.y;
    int tid = threadIdx.x;
    int c = tid & 63, g = tid >> 6;  // 4 groups
    const __half* hp = h + ((size_t)b * NPG * 8 + t) * 64 + c;
    float mx = -1e30f, sm = 0.f;
    for (int i = g; i < NPG; i += 4) {
        float v = __half2float(hp[(size_t)i * 512]);
        mx = fmaxf(mx, v);
        sm += v;
    }
    __shared__ float smx[4][64], ssm[4][64];
    smx[g][c] = mx; ssm[g][c] = sm;
    __syncthreads();
    if (tid < 64) {
        float m = fmaxf(fmaxf(smx[0][tid], smx[1][tid]),
                        fmaxf(smx[2][tid], smx[3][tid]));
        float s = (ssm[0][tid] + ssm[1][tid] + ssm[2][tid] + ssm[3][tid])
                  * (1.f / (float)NPG);
        if (FIRST) {
            out[b * 1024 + tid * 8 + t]        = m;
            out[b * 1024 + (64 + tid) * 8 + t] = s;
        } else {
            out[b * 1024 + tid * 8 + t]        += m;
            out[b * 1024 + (64 + tid) * 8 + t] += s;
        }
    }
}

// ---------------- launch -----------------------------------------------------
extern "C" void kernel_launch(void* const* d_in, const int* in_sizes, int n_in,
                              void* d_out, int out_size) {
    const float* x  = (const float*)d_in[0];
    const int*   ei = (const int*)d_in[1];     // int32 [2, E]
    const float* W1 = (const float*)d_in[3];
    const float* b1 = (const float*)d_in[4];
    const float* W2 = (const float*)d_in[5];
    const float* b2 = (const float*)d_in[6];
    const float* W3 = (const float*)d_in[7];
    const float* b3 = (const float*)d_in[8];
    float* out = (float*)d_out;

    __half *agg, *h, *w1h, *w2h, *w3h;
    cudaGetSymbolAddress((void**)&agg, g_agg);
    cudaGetSymbolAddress((void**)&h,   g_h);
    cudaGetSymbolAddress((void**)&w1h, g_W1h);
    cudaGetSymbolAddress((void**)&w2h, g_W2h);
    cudaGetSymbolAddress((void**)&w3h, g_W3h);

    // setup
    setup_a_kernel<<<(N_NODES * C_IN + 255) / 256, 256>>>(x, W1, W2, W3);
    count_deg_kernel<<<(N_EDGES + 255) / 256, 256>>>(ei);
    scan_part_kernel<<<SCAN_NBLK, 256>>>();
    scan_finish_kernel<<<1, 1024>>>();
    fill_csr_kernel<<<(N_EDGES + 255) / 256, 256>>>(ei);

    const int AGG_GRID  = N_NODES / 8;        // 8 warps/block, warp=node
    const int GEMM_GRID = M_ALL / 128;        // 3125
    dim3 pool_grid(NB, NT);

    // layer 1
    agg32_all_kernel<<<AGG_GRID, 256>>>((uint4*)agg);
    hgemm_bias_relu_kernel<32><<<GEMM_GRID, 256>>>(agg, w1h, b1, h);
    pool_all_kernel<true><<<pool_grid, 256>>>(h, out);
    // layer 2
    agg64_all_kernel<<<AGG_GRID, 256>>>((const uint4*)h, (uint4*)agg);
    hgemm_bias_relu_kernel<64><<<GEMM_GRID, 256>>>(agg, w2h, b2, h);
    pool_all_kernel<false><<<pool_grid, 256>>>(h, out);
    // layer 3
    agg64_all_kernel<<<AGG_GRID, 256>>>((const uint4*)h, (uint4*)agg);
    hgemm_bias_relu_kernel<64><<<GEMM_GRID, 256>>>(agg, w3h, b3, h);
    pool_all_kernel<false><<<pool_grid, 256>>>(h, out);
}

// round 13
// speedup vs baseline: 1.9931x; 1.2796x over previous
#include <cuda_runtime.h>
#include <cuda_fp16.h>
#include <math.h>
#include <stdint.h>

#define N_NODES 50000
#define N_EDGES 800000
#define NB      250
#define NT      8
#define C_IN    32
#define C_OUT   64
#define NPG     200   // nodes per graph (contiguous)
#define M_ALL   (NT * N_NODES)       // 400000 rows = n*8+t
#define SCAN_NBLK ((N_NODES + 255) / 256)   // 196

// ---------------- scratch (static device globals; no allocation) -------------
__device__ __half g_xh[(size_t)N_NODES * NT * C_IN];    // [n][t][c] fp16 (row 512B)
__device__ __half g_hA[(size_t)N_NODES * NT * C_OUT];   // ping
__device__ __half g_hB[(size_t)N_NODES * NT * C_OUT];   // pong
__device__ uint2  g_Wf1[2 * 8 * 32];   // W1 MMA fragments [ks][j][lane]
__device__ uint2  g_Wf2[4 * 8 * 32];
__device__ uint2  g_Wf3[4 * 8 * 32];
__device__ int    g_deg[N_NODES];      // zero-init at load; re-zeroed by fused<32>
__device__ int    g_cnt[N_NODES];
__device__ int    g_rowptr[N_NODES + 1];
__device__ int    g_bsum[SCAN_NBLK];
__device__ int    g_boff[256];
__device__ float  g_dinv[N_NODES];
__device__ int    g_src[N_EDGES];
__device__ float  g_norm[N_EDGES];

// ---------------- helpers ----------------------------------------------------
__device__ __forceinline__ float2 u2f(uint32_t u) {
    __half2 h = *(__half2*)&u;
    return __half22float2(h);
}
__device__ __forceinline__ uint32_t f2u(float a, float b) {
    __half2 h = __floats2half2_rn(a, b);
    return *(uint32_t*)&h;
}
__device__ __forceinline__ uint32_t pack_h2f(float a, float b) { return f2u(a, b); }

// ---------------- setup: W frags + transpose x + count_deg -------------------
// NOTE: g_deg/g_cnt are NOT zeroed here. They are zero at module load and
// re-zeroed at the end of each pipeline by fused<32> (after fill_csr).
__device__ __forceinline__ void wfrag_store(uint2* Wf, const float* W, int rem) {
    // rem = ks*256 + j*32 + lane
    int ks = rem >> 8, j = (rem >> 5) & 7, lane = rem & 31;
    int lq = lane >> 2, lr = lane & 3;
    int n = j * 8 + lq;
    int kb = ks * 16 + lr * 2;
    uint2 f;
    f.x = f2u(W[kb * 64 + n],       W[(kb + 1) * 64 + n]);
    f.y = f2u(W[(kb + 8) * 64 + n], W[(kb + 9) * 64 + n]);
    Wf[rem] = f;
}

__global__ void setup_all_kernel(const float* __restrict__ x,
                                 const int* __restrict__ ei,
                                 const float* __restrict__ W1,
                                 const float* __restrict__ W2,
                                 const float* __restrict__ W3) {
    int i = blockIdx.x * blockDim.x + threadIdx.x;
    if (i < 512)                    wfrag_store(g_Wf1, W1, i);
    else if (i >= 1024 && i < 2048) wfrag_store(g_Wf2, W2, i - 1024);
    else if (i >= 2048 && i < 3072) wfrag_store(g_Wf3, W3, i - 2048);
    if (i < N_EDGES) {
        int dst = ei[N_EDGES + i];
        if ((unsigned)dst < (unsigned)N_NODES)
            atomicAdd(&g_deg[dst], 1);
    }
    if (i >= N_NODES * C_IN) return;
    // transpose: x[N, C_IN, T] -> g_xh [n][t][c]
    int n = i / C_IN, c = i % C_IN;
    const float4* p = (const float4*)(x + (size_t)i * NT);
    float4 a = p[0], b4 = p[1];
    float v[8] = {a.x, a.y, a.z, a.w, b4.x, b4.y, b4.z, b4.w};
#pragma unroll
    for (int t = 0; t < NT; t++)
        g_xh[(size_t)n * (NT * C_IN) + t * C_IN + c] = __float2half_rn(v[t]);
}

// ---------------- parallel scan --------------------------------------------
__global__ void __launch_bounds__(256) scan_part_kernel() {
    __shared__ int ws[8];
    int b = blockIdx.x, tid = threadIdx.x;
    int i = b * 256 + tid;
    int lane = tid & 31, wid = tid >> 5;
    int v = (i < N_NODES) ? g_deg[i] : 0;
    if (i < N_NODES) g_dinv[i] = rsqrtf((float)(v + 1));  // +1 self loop
    int x = v;
#pragma unroll
    for (int off = 1; off < 32; off <<= 1) {
        int y = __shfl_up_sync(0xffffffffu, x, off);
        if (lane >= off) x += y;
    }
    if (lane == 31) ws[wid] = x;
    __syncthreads();
    if (tid < 8) {
        int s = ws[tid];
#pragma unroll
        for (int off = 1; off < 8; off <<= 1) {
            int y = __shfl_up_sync(0x000000ffu, s, off);
            if (tid >= off) s += y;
        }
        ws[tid] = s;
    }
    __syncthreads();
    int woff = wid ? ws[wid - 1] : 0;
    if (i < N_NODES) g_rowptr[i] = woff + x - v;   // local exclusive
    if (tid == 0) g_bsum[b] = ws[7];
}

// 1 block, 256 threads: exclusive scan of the 196 block sums -> g_boff
__global__ void __launch_bounds__(256) scan_bsum_kernel() {
    __shared__ int wsum[8];
    int tid = threadIdx.x;
    int lane = tid & 31, wid = tid >> 5;
    int v = (tid < SCAN_NBLK) ? g_bsum[tid] : 0;
    int x = v;
#pragma unroll
    for (int off = 1; off < 32; off <<= 1) {
        int y = __shfl_up_sync(0xffffffffu, x, off);
        if (lane >= off) x += y;
    }
    if (lane == 31) wsum[wid] = x;
    __syncthreads();
    if (tid == 0) {
        int run = 0;
#pragma unroll
        for (int w = 0; w < 8; w++) { int s = wsum[w]; wsum[w] = run; run += s; }
        g_rowptr[N_NODES] = run;
    }
    __syncthreads();
    g_boff[tid] = wsum[wid] + x - v;   // exclusive across blocks
}

__global__ void __launch_bounds__(1024) scan_apply_kernel() {
    int i = blockIdx.x * 1024 + threadIdx.x;
    if (i < N_NODES) g_rowptr[i] += g_boff[i >> 8];
}

__global__ void fill_csr_kernel(const int* __restrict__ ei) {
    int e = blockIdx.x * blockDim.x + threadIdx.x;
    if (e >= N_EDGES) return;
    int src = ei[e];
    int dst = ei[N_EDGES + e];
    if ((unsigned)src >= (unsigned)N_NODES ||
        (unsigned)dst >= (unsigned)N_NODES) return;
    int pos = g_rowptr[dst] + atomicAdd(&g_cnt[dst], 1);
    if ((unsigned)pos < (unsigned)N_EDGES) {
        g_src[pos]  = src;
        g_norm[pos] = g_dinv[src] * g_dinv[dst];
    }
}

// ---------------- fused warp-local aggregation + HMMA GEMM -------------------
// Block = 16 nodes, 8 warps; warp = 2 nodes = 16 GEMM rows (r = n*8+t).
// Phase A (per warp, no block barrier): CSR-gather each node's [8t x K] fp16
// row block into fp32 regs, store fp16 tile into warp-private padded smem.
// Phase B: __syncwarp, then 16x64 HMMA GEMM (KS k-steps x 8 n-tiles) with
// pre-packed W fragments; bias+relu epilogue to gmem [n][t][c].
// in and out MUST be distinct buffers (cross-block neighbor reads of `in`).
template <int K, bool CLEANUP>
__global__ void __launch_bounds__(256) fused_agg_gemm_kernel(
    const uint4* __restrict__ in, const uint2* __restrict__ Wf,
    const float* __restrict__ bias, __half* __restrict__ out) {
    constexpr int NU  = K / 32;          // uint4 per lane per node-row
    constexpr int C2  = K / 2;           // half2 per GEMM row
    constexpr int PAD = (K == 64) ? 36 : 20;
    constexpr int KS  = K / 16;
    constexpr int TSH = (K == 64) ? 5 : 4;   // f>>TSH = t
    __shared__ uint32_t As[8 * 16 * PAD];

    int tid = threadIdx.x, lane = tid & 31, warp = tid >> 5;

    if (CLEANUP) {   // re-zero deg/cnt for the next replay (post fill_csr)
        int gi = blockIdx.x * 256 + tid;
        if (gi < N_NODES) { g_deg[gi] = 0; g_cnt[gi] = 0; }
    }

    uint32_t* Aw = As + warp * 16 * PAD;

    // ---- phase A: gather 2 nodes ----
#pragma unroll
    for (int ln = 0; ln < 2; ln++) {
        int n = blockIdx.x * 16 + warp * 2 + ln;
        float dv = g_dinv[n];
        float dv2 = dv * dv;
        float2 acc[NU * 4];
#pragma unroll
        for (int u = 0; u < NU; u++) {
            uint4 v = __ldg(&in[(size_t)n * (NU * 32) + u * 32 + lane]);
            uint32_t uu[4] = {v.x, v.y, v.z, v.w};
#pragma unroll
            for (int q = 0; q < 4; q++) {
                float2 f = u2f(uu[q]);
                acc[u * 4 + q].x = dv2 * f.x;
                acc[u * 4 + q].y = dv2 * f.y;
            }
        }
        int s = g_rowptr[n], e2 = g_rowptr[n + 1];
        for (int base = s; base < e2; base += 32) {
            int idx = base + lane;
            int sl = 0; float nl = 0.f;
            if (idx < e2) { sl = g_src[idx]; nl = g_norm[idx]; }
            int cnt = min(32, e2 - base);
            int j = 0;
            for (; j + 2 <= cnt; j += 2) {
                int s0 = __shfl_sync(0xffffffffu, sl, j);
                int s1 = __shfl_sync(0xffffffffu, sl, j + 1);
                float w0 = __shfl_sync(0xffffffffu, nl, j);
                float w1 = __shfl_sync(0xffffffffu, nl, j + 1);
                uint4 va[NU], vb[NU];
#pragma unroll
                for (int u = 0; u < NU; u++) {
                    va[u] = __ldg(&in[(size_t)s0 * (NU * 32) + u * 32 + lane]);
                    vb[u] = __ldg(&in[(size_t)s1 * (NU * 32) + u * 32 + lane]);
                }
#pragma unroll
                for (int u = 0; u < NU; u++) {
                    uint32_t ua[4] = {va[u].x, va[u].y, va[u].z, va[u].w};
                    uint32_t ub[4] = {vb[u].x, vb[u].y, vb[u].z, vb[u].w};
#pragma unroll
                    for (int q = 0; q < 4; q++) {
                        float2 fa = u2f(ua[q]), fb = u2f(ub[q]);
                        acc[u * 4 + q].x = fmaf(w0, fa.x, acc[u * 4 + q].x);
                        acc[u * 4 + q].y = fmaf(w0, fa.y, acc[u * 4 + q].y);
                        acc[u * 4 + q].x = fmaf(w1, fb.x, acc[u * 4 + q].x);
                        acc[u * 4 + q].y = fmaf(w1, fb.y, acc[u * 4 + q].y);
                    }
                }
            }
            for (; j < cnt; j++) {
                int src  = __shfl_sync(0xffffffffu, sl, j);
                float wt = __shfl_sync(0xffffffffu, nl, j);
#pragma unroll
                for (int u = 0; u < NU; u++) {
                    uint4 v = __ldg(&in[(size_t)src * (NU * 32) + u * 32 + lane]);
                    uint32_t uu[4] = {v.x, v.y, v.z, v.w};
#pragma unroll
                    for (int q = 0; q < 4; q++) {
                        float2 f = u2f(uu[q]);
                        acc[u * 4 + q].x = fmaf(wt, f.x, acc[u * 4 + q].x);
                        acc[u * 4 + q].y = fmaf(wt, f.y, acc[u * 4 + q].y);
                    }
                }
            }
        }
        // store to warp-private smem tile (uint4 = 4 consecutive half2)
#pragma unroll
        for (int u = 0; u < NU; u++) {
            int f = (lane + u * 32) * 4;
            int t = f >> TSH;
            int c2 = f & (C2 - 1);
            uint4 o;
            o.x = f2u(acc[u * 4 + 0].x, acc[u * 4 + 0].y);
            o.y = f2u(acc[u * 4 + 1].x, acc[u * 4 + 1].y);
            o.z = f2u(acc[u * 4 + 2].x, acc[u * 4 + 2].y);
            o.w = f2u(acc[u * 4 + 3].x, acc[u * 4 + 3].y);
            *(uint4*)(Aw + (ln * 8 + t) * PAD + c2) = o;
        }
    }
    __syncwarp();

    // ---- phase B: 16x64 HMMA GEMM ----
    int lq = lane >> 2, lr = lane & 3;
    float acc2[8][4];
#pragma unroll
    for (int j = 0; j < 8; j++)
#pragma unroll
        for (int q = 0; q < 4; q++) acc2[j][q] = 0.f;

#pragma unroll
    for (int ks = 0; ks < KS; ks++) {
        int c2a = ks * 8 + lr;
        uint32_t a0 = Aw[lq * PAD + c2a];
        uint32_t a1 = Aw[(lq + 8) * PAD + c2a];
        uint32_t a2 = Aw[lq * PAD + c2a + 4];
        uint32_t a3 = Aw[(lq + 8) * PAD + c2a + 4];
#pragma unroll
        for (int j = 0; j < 8; j++) {
            uint2 bf = __ldg(&Wf[ks * 256 + j * 32 + lane]);
            asm volatile(
                "mma.sync.aligned.m16n8k16.row.col.f32.f16.f16.f32 "
                "{%0,%1,%2,%3}, {%4,%5,%6,%7}, {%8,%9}, {%0,%1,%2,%3};"
                : "+f"(acc2[j][0]), "+f"(acc2[j][1]),
                  "+f"(acc2[j][2]), "+f"(acc2[j][3])
                : "r"(a0), "r"(a1), "r"(a2), "r"(a3),
                  "r"(bf.x), "r"(bf.y));
        }
    }

    // epilogue: bias + relu, fp16 store
    size_t row0 = (size_t)blockIdx.x * 128 + warp * 16;
#pragma unroll
    for (int j = 0; j < 8; j++) {
        int c = j * 8 + lr * 2;
        float bx = bias[c], by = bias[c + 1];
        float ox = fmaxf(acc2[j][0] + bx, 0.f);
        float oy = fmaxf(acc2[j][1] + by, 0.f);
        *(__half2*)(out + (row0 + lq) * 64 + c) = __floats2half2_rn(ox, oy);
        float oz = fmaxf(acc2[j][2] + bx, 0.f);
        float ow = fmaxf(acc2[j][3] + by, 0.f);
        *(__half2*)(out + (row0 + lq + 8) * 64 + c) = __floats2half2_rn(oz, ow);
    }
}

// ---------------- pooling: out[b, c, t] (max) and [b, 64+c, t] (mean) --------
template <bool FIRST>
__global__ void __launch_bounds__(256) pool_all_kernel(const __half* __restrict__ h,
                                                       float* __restrict__ out) {
    int b = blockIdx.x, t = blockIdx.y;
    int tid = threadIdx.x;
    int c = tid & 63, g = tid >> 6;  // 4 groups
    const __half* hp = h + ((size_t)b * NPG * 8 + t) * 64 + c;
    float mx = -1e30f, sm = 0.f;
    for (int i = g; i < NPG; i += 4) {
        float v = __half2float(hp[(size_t)i * 512]);
        mx = fmaxf(mx, v);
        sm += v;
    }
    __shared__ float smx[4][64], ssm[4][64];
    smx[g][c] = mx; ssm[g][c] = sm;
    __syncthreads();
    if (tid < 64) {
        float m = fmaxf(fmaxf(smx[0][tid], smx[1][tid]),
                        fmaxf(smx[2][tid], smx[3][tid]));
        float s = (ssm[0][tid] + ssm[1][tid] + ssm[2][tid] + ssm[3][tid])
                  * (1.f / (float)NPG);
        if (FIRST) {
            out[b * 1024 + tid * 8 + t]        = m;
            out[b * 1024 + (64 + tid) * 8 + t] = s;
        } else {
            out[b * 1024 + tid * 8 + t]        += m;
            out[b * 1024 + (64 + tid) * 8 + t] += s;
        }
    }
}

// ---------------- launch -----------------------------------------------------
extern "C" void kernel_launch(void* const* d_in, const int* in_sizes, int n_in,
                              void* d_out, int out_size) {
    const float* x  = (const float*)d_in[0];
    const int*   ei = (const int*)d_in[1];     // int32 [2, E]
    const float* W1 = (const float*)d_in[3];
    const float* b1 = (const float*)d_in[4];
    const float* W2 = (const float*)d_in[5];
    const float* b2 = (const float*)d_in[6];
    const float* W3 = (const float*)d_in[7];
    const float* b3 = (const float*)d_in[8];
    float* out = (float*)d_out;

    __half *xh, *hA, *hB;
    uint2 *wf1, *wf2, *wf3;
    cudaGetSymbolAddress((void**)&xh,  g_xh);
    cudaGetSymbolAddress((void**)&hA,  g_hA);
    cudaGetSymbolAddress((void**)&hB,  g_hB);
    cudaGetSymbolAddress((void**)&wf1, g_Wf1);
    cudaGetSymbolAddress((void**)&wf2, g_Wf2);
    cudaGetSymbolAddress((void**)&wf3, g_Wf3);

    // setup (deg/cnt are zero: module load on call 1, fused<32> thereafter)
    setup_all_kernel<<<(N_NODES * C_IN + 255) / 256, 256>>>(x, ei, W1, W2, W3);
    scan_part_kernel<<<SCAN_NBLK, 256>>>();
    scan_bsum_kernel<<<1, 256>>>();
    scan_apply_kernel<<<(N_NODES + 1023) / 1024, 1024>>>();
    fill_csr_kernel<<<(N_EDGES + 255) / 256, 256>>>(ei);

    const int FUSE_GRID = N_NODES / 16;   // 3125 blocks, 16 nodes, 8 warps
    dim3 pool_grid(NB, NT);

    // layer 1: xh -> hA  (+ deg/cnt cleanup for next replay)
    fused_agg_gemm_kernel<32, true><<<FUSE_GRID, 256>>>((const uint4*)xh, wf1, b1, hA);
    pool_all_kernel<true><<<pool_grid, 256>>>(hA, out);
    // layer 2: hA -> hB
    fused_agg_gemm_kernel<64, false><<<FUSE_GRID, 256>>>((const uint4*)hA, wf2, b2, hB);
    pool_all_kernel<false><<<pool_grid, 256>>>(hB, out);
    // layer 3: hB -> hA
    fused_agg_gemm_kernel<64, false><<<FUSE_GRID, 256>>>((const uint4*)hB, wf3, b3, hA);
    pool_all_kernel<false><<<pool_grid, 256>>>(hA, out);
}

// round 15
// speedup vs baseline: 2.1461x; 1.0768x over previous
#include <cuda_runtime.h>
#include <cuda_fp16.h>
#include <math.h>
#include <stdint.h>

#define N_NODES 50000
#define N_EDGES 800000
#define NB      250
#define NT      8
#define C_IN    32
#define C_OUT   64
#define NPG     200   // nodes per graph (contiguous)
#define SCAN_NBLK ((N_NODES + 255) / 256)   // 196

// ---------------- scratch (static device globals; no allocation) -------------
__device__ __half g_xh[(size_t)N_NODES * NT * C_IN];    // [n][t][c] fp16 (row 512B)
__device__ __half g_hA[(size_t)N_NODES * NT * C_OUT];   // ping
__device__ __half g_hB[(size_t)N_NODES * NT * C_OUT];   // pong
__device__ uint2  g_Wf1[2 * 8 * 32];   // W1 MMA fragments [ks][j][lane]
__device__ uint2  g_Wf2[4 * 8 * 32];
__device__ uint2  g_Wf3[4 * 8 * 32];
__device__ int    g_deg[N_NODES];      // zero-init at load; re-zeroed by fused<32>
__device__ int    g_cnt[N_NODES];
__device__ int    g_rowptr[N_NODES + 1];
__device__ int    g_bsum[SCAN_NBLK];
__device__ float  g_dinv[N_NODES];
__device__ uint2  g_edge[N_EDGES];     // {src, norm bits}

// ---------------- helpers ----------------------------------------------------
__device__ __forceinline__ float2 u2f(uint32_t u) {
    __half2 h = *(__half2*)&u;
    return __half22float2(h);
}
__device__ __forceinline__ uint32_t f2u(float a, float b) {
    __half2 h = __floats2half2_rn(a, b);
    return *(uint32_t*)&h;
}

// ---------------- setup: W frags + transpose x + count_deg -------------------
// g_deg/g_cnt zero at module load (call 1) and re-zeroed by fused<32> after.
__device__ __forceinline__ void wfrag_store(uint2* Wf, const float* W, int rem) {
    int ks = rem >> 8, j = (rem >> 5) & 7, lane = rem & 31;
    int lq = lane >> 2, lr = lane & 3;
    int n = j * 8 + lq;
    int kb = ks * 16 + lr * 2;
    uint2 f;
    f.x = f2u(W[kb * 64 + n],       W[(kb + 1) * 64 + n]);
    f.y = f2u(W[(kb + 8) * 64 + n], W[(kb + 9) * 64 + n]);
    Wf[rem] = f;
}

__global__ void setup_all_kernel(const float* __restrict__ x,
                                 const int* __restrict__ ei,
                                 const float* __restrict__ W1,
                                 const float* __restrict__ W2,
                                 const float* __restrict__ W3) {
    int i = blockIdx.x * blockDim.x + threadIdx.x;
    if (i < 512)                    wfrag_store(g_Wf1, W1, i);
    else if (i >= 1024 && i < 2048) wfrag_store(g_Wf2, W2, i - 1024);
    else if (i >= 2048 && i < 3072) wfrag_store(g_Wf3, W3, i - 2048);
    if (i < N_EDGES) {
        int dst = ei[N_EDGES + i];
        if ((unsigned)dst < (unsigned)N_NODES)
            atomicAdd(&g_deg[dst], 1);
    }
    if (i >= N_NODES * C_IN) return;
    int n = i / C_IN, c = i % C_IN;
    const float4* p = (const float4*)(x + (size_t)i * NT);
    float4 a = p[0], b4 = p[1];
    float v[8] = {a.x, a.y, a.z, a.w, b4.x, b4.y, b4.z, b4.w};
#pragma unroll
    for (int t = 0; t < NT; t++)
        g_xh[(size_t)n * (NT * C_IN) + t * C_IN + c] = __float2half_rn(v[t]);
}

// ---------------- parallel scan ---------------------------------------------
__global__ void __launch_bounds__(256) scan_part_kernel() {
    __shared__ int ws[8];
    int b = blockIdx.x, tid = threadIdx.x;
    int i = b * 256 + tid;
    int lane = tid & 31, wid = tid >> 5;
    int v = (i < N_NODES) ? g_deg[i] : 0;
    if (i < N_NODES) g_dinv[i] = rsqrtf((float)(v + 1));  // +1 self loop
    int x = v;
#pragma unroll
    for (int off = 1; off < 32; off <<= 1) {
        int y = __shfl_up_sync(0xffffffffu, x, off);
        if (lane >= off) x += y;
    }
    if (lane == 31) ws[wid] = x;
    __syncthreads();
    if (tid < 8) {
        int s = ws[tid];
#pragma unroll
        for (int off = 1; off < 8; off <<= 1) {
            int y = __shfl_up_sync(0x000000ffu, s, off);
            if (tid >= off) s += y;
        }
        ws[tid] = s;
    }
    __syncthreads();
    int woff = wid ? ws[wid - 1] : 0;
    if (i < N_NODES) g_rowptr[i] = woff + x - v;   // local exclusive
    if (tid == 0) g_bsum[b] = ws[7];
}

// grid 49 x 1024: each block redundantly scans the 196 block sums (cheap),
// then applies offsets to its 1024-node range. Cross-warp edges use
// __syncthreads (R11 lesson).
__global__ void __launch_bounds__(1024) scan_apply_kernel() {
    __shared__ int boff[256];
    __shared__ int wsum[8];
    int tid = threadIdx.x;
    int lane = tid & 31, wid = tid >> 5;
    int v = 0, x = 0;
    if (tid < 256) {
        v = (tid < SCAN_NBLK) ? g_bsum[tid] : 0;
        x = v;
#pragma unroll
        for (int off = 1; off < 32; off <<= 1) {
            int y = __shfl_up_sync(0xffffffffu, x, off);
            if (lane >= off) x += y;
        }
        if (lane == 31) wsum[wid] = x;
    }
    __syncthreads();
    if (tid == 0) {
        int run = 0;
#pragma unroll
        for (int w = 0; w < 8; w++) { int s = wsum[w]; wsum[w] = run; run += s; }
        if (blockIdx.x == 0) g_rowptr[N_NODES] = run;
    }
    __syncthreads();
    if (tid < 256)
        boff[tid] = wsum[wid] + x - v;
    __syncthreads();
    int i = blockIdx.x * 1024 + tid;
    if (i < N_NODES) g_rowptr[i] += boff[i >> 8];
}

__global__ void fill_csr_kernel(const int* __restrict__ ei) {
    int e = blockIdx.x * blockDim.x + threadIdx.x;
    if (e >= N_EDGES) return;
    int src = ei[e];
    int dst = ei[N_EDGES + e];
    if ((unsigned)src >= (unsigned)N_NODES ||
        (unsigned)dst >= (unsigned)N_NODES) return;
    int pos = g_rowptr[dst] + atomicAdd(&g_cnt[dst], 1);
    if ((unsigned)pos < (unsigned)N_EDGES) {
        uint2 rec;
        rec.x = (uint32_t)src;
        rec.y = __float_as_uint(g_dinv[src] * g_dinv[dst]);
        g_edge[pos] = rec;
    }
}

// ---------------- fused warp-local aggregation + HMMA GEMM -------------------
// Block = 16 nodes, 8 warps; warp = 2 nodes = 16 GEMM rows (r = n*8+t).
// Phase A: warp-private CSR gather (no block barrier) -> fp16 smem tile.
// Phase B: __syncwarp, 16x64 HMMA GEMM with pre-packed W fragments.
// in and out MUST be distinct buffers.
template <int K, bool CLEANUP>
__global__ void __launch_bounds__(256) fused_agg_gemm_kernel(
    const uint4* __restrict__ in, const uint2* __restrict__ Wf,
    const float* __restrict__ bias, __half* __restrict__ out) {
    constexpr int NU  = K / 32;          // uint4 per lane per node-row
    constexpr int C2  = K / 2;           // half2 per GEMM row
    constexpr int PAD = (K == 64) ? 36 : 20;
    constexpr int KS  = K / 16;
    constexpr int TSH = (K == 64) ? 5 : 4;   // f>>TSH = t
    __shared__ uint32_t As[8 * 16 * PAD];

    int tid = threadIdx.x, lane = tid & 31, warp = tid >> 5;

    if (CLEANUP) {   // re-zero deg/cnt for the next replay (post fill_csr)
        int gi = blockIdx.x * 256 + tid;
        if (gi < N_NODES) { g_deg[gi] = 0; g_cnt[gi] = 0; }
    }

    uint32_t* Aw = As + warp * 16 * PAD;

    // ---- phase A: gather 2 nodes ----
#pragma unroll
    for (int ln = 0; ln < 2; ln++) {
        int n = blockIdx.x * 16 + warp * 2 + ln;
        float dv = g_dinv[n];
        float dv2 = dv * dv;
        float2 acc[NU * 4];
#pragma unroll
        for (int u = 0; u < NU; u++) {
            uint4 v = __ldg(&in[(size_t)n * (NU * 32) + u * 32 + lane]);
            uint32_t uu[4] = {v.x, v.y, v.z, v.w};
#pragma unroll
            for (int q = 0; q < 4; q++) {
                float2 f = u2f(uu[q]);
                acc[u * 4 + q].x = dv2 * f.x;
                acc[u * 4 + q].y = dv2 * f.y;
            }
        }
        int s = g_rowptr[n], e2 = g_rowptr[n + 1];
        for (int base = s; base < e2; base += 32) {
            int idx = base + lane;
            int sl = 0; float nl = 0.f;
            if (idx < e2) {
                uint2 rec = __ldg(&g_edge[idx]);
                sl = (int)rec.x; nl = __uint_as_float(rec.y);
            }
            int cnt = min(32, e2 - base);
            int j = 0;
            if (K == 32) {
                for (; j + 4 <= cnt; j += 4) {   // 4-edge unroll (MLP=4)
                    int s0 = __shfl_sync(0xffffffffu, sl, j);
                    int s1 = __shfl_sync(0xffffffffu, sl, j + 1);
                    int s2 = __shfl_sync(0xffffffffu, sl, j + 2);
                    int s3 = __shfl_sync(0xffffffffu, sl, j + 3);
                    float w0 = __shfl_sync(0xffffffffu, nl, j);
                    float w1 = __shfl_sync(0xffffffffu, nl, j + 1);
                    float w2 = __shfl_sync(0xffffffffu, nl, j + 2);
                    float w3 = __shfl_sync(0xffffffffu, nl, j + 3);
                    uint4 v0 = __ldg(&in[(size_t)s0 * 32 + lane]);
                    uint4 v1 = __ldg(&in[(size_t)s1 * 32 + lane]);
                    uint4 v2 = __ldg(&in[(size_t)s2 * 32 + lane]);
                    uint4 v3 = __ldg(&in[(size_t)s3 * 32 + lane]);
                    uint32_t u0[4] = {v0.x, v0.y, v0.z, v0.w};
                    uint32_t u1[4] = {v1.x, v1.y, v1.z, v1.w};
                    uint32_t u2[4] = {v2.x, v2.y, v2.z, v2.w};
                    uint32_t u3[4] = {v3.x, v3.y, v3.z, v3.w};
#pragma unroll
                    for (int q = 0; q < 4; q++) {
                        float2 f0 = u2f(u0[q]), f1 = u2f(u1[q]);
                        float2 f2 = u2f(u2[q]), f3 = u2f(u3[q]);
                        acc[q].x = fmaf(w0, f0.x, acc[q].x); acc[q].y = fmaf(w0, f0.y, acc[q].y);
                        acc[q].x = fmaf(w1, f1.x, acc[q].x); acc[q].y = fmaf(w1, f1.y, acc[q].y);
                        acc[q].x = fmaf(w2, f2.x, acc[q].x); acc[q].y = fmaf(w2, f2.y, acc[q].y);
                        acc[q].x = fmaf(w3, f3.x, acc[q].x); acc[q].y = fmaf(w3, f3.y, acc[q].y);
                    }
                }
            } else {
                for (; j + 2 <= cnt; j += 2) {   // 2-edge unroll (MLP=4 loads)
                    int s0 = __shfl_sync(0xffffffffu, sl, j);
                    int s1 = __shfl_sync(0xffffffffu, sl, j + 1);
                    float w0 = __shfl_sync(0xffffffffu, nl, j);
                    float w1 = __shfl_sync(0xffffffffu, nl, j + 1);
                    uint4 va[NU], vb[NU];
#pragma unroll
                    for (int u = 0; u < NU; u++) {
                        va[u] = __ldg(&in[(size_t)s0 * (NU * 32) + u * 32 + lane]);
                        vb[u] = __ldg(&in[(size_t)s1 * (NU * 32) + u * 32 + lane]);
                    }
#pragma unroll
                    for (int u = 0; u < NU; u++) {
                        uint32_t ua[4] = {va[u].x, va[u].y, va[u].z, va[u].w};
                        uint32_t ub[4] = {vb[u].x, vb[u].y, vb[u].z, vb[u].w};
#pragma unroll
                        for (int q = 0; q < 4; q++) {
                            float2 fa = u2f(ua[q]), fb = u2f(ub[q]);
                            acc[u * 4 + q].x = fmaf(w0, fa.x, acc[u * 4 + q].x);
                            acc[u * 4 + q].y = fmaf(w0, fa.y, acc[u * 4 + q].y);
                            acc[u * 4 + q].x = fmaf(w1, fb.x, acc[u * 4 + q].x);
                            acc[u * 4 + q].y = fmaf(w1, fb.y, acc[u * 4 + q].y);
                        }
                    }
                }
            }
            for (; j < cnt; j++) {
                int src  = __shfl_sync(0xffffffffu, sl, j);
                float wt = __shfl_sync(0xffffffffu, nl, j);
#pragma unroll
                for (int u = 0; u < NU; u++) {
                    uint4 v = __ldg(&in[(size_t)src * (NU * 32) + u * 32 + lane]);
                    uint32_t uu[4] = {v.x, v.y, v.z, v.w};
#pragma unroll
                    for (int q = 0; q < 4; q++) {
                        float2 f = u2f(uu[q]);
                        acc[u * 4 + q].x = fmaf(wt, f.x, acc[u * 4 + q].x);
                        acc[u * 4 + q].y = fmaf(wt, f.y, acc[u * 4 + q].y);
                    }
                }
            }
        }
        // store to warp-private smem tile (uint4 = 4 consecutive half2)
#pragma unroll
        for (int u = 0; u < NU; u++) {
            int f = (lane + u * 32) * 4;
            int t = f >> TSH;
            int c2 = f & (C2 - 1);
            uint4 o;
            o.x = f2u(acc[u * 4 + 0].x, acc[u * 4 + 0].y);
            o.y = f2u(acc[u * 4 + 1].x, acc[u * 4 + 1].y);
            o.z = f2u(acc[u * 4 + 2].x, acc[u * 4 + 2].y);
            o.w = f2u(acc[u * 4 + 3].x, acc[u * 4 + 3].y);
            *(uint4*)(Aw + (ln * 8 + t) * PAD + c2) = o;
        }
    }
    __syncwarp();

    // ---- phase B: 16x64 HMMA GEMM ----
    int lq = lane >> 2, lr = lane & 3;
    float acc2[8][4];
#pragma unroll
    for (int j = 0; j < 8; j++)
#pragma unroll
        for (int q = 0; q < 4; q++) acc2[j][q] = 0.f;

#pragma unroll
    for (int ks = 0; ks < KS; ks++) {
        int c2a = ks * 8 + lr;
        uint32_t a0 = Aw[lq * PAD + c2a];
        uint32_t a1 = Aw[(lq + 8) * PAD + c2a];
        uint32_t a2 = Aw[lq * PAD + c2a + 4];
        uint32_t a3 = Aw[(lq + 8) * PAD + c2a + 4];
#pragma unroll
        for (int j = 0; j < 8; j++) {
            uint2 bf = __ldg(&Wf[ks * 256 + j * 32 + lane]);
            asm volatile(
                "mma.sync.aligned.m16n8k16.row.col.f32.f16.f16.f32 "
                "{%0,%1,%2,%3}, {%4,%5,%6,%7}, {%8,%9}, {%0,%1,%2,%3};"
                : "+f"(acc2[j][0]), "+f"(acc2[j][1]),
                  "+f"(acc2[j][2]), "+f"(acc2[j][3])
                : "r"(a0), "r"(a1), "r"(a2), "r"(a3),
                  "r"(bf.x), "r"(bf.y));
        }
    }

    // epilogue: bias + relu, fp16 store
    size_t row0 = (size_t)blockIdx.x * 128 + warp * 16;
#pragma unroll
    for (int j = 0; j < 8; j++) {
        int c = j * 8 + lr * 2;
        float bx = bias[c], by = bias[c + 1];
        float ox = fmaxf(acc2[j][0] + bx, 0.f);
        float oy = fmaxf(acc2[j][1] + by, 0.f);
        *(__half2*)(out + (row0 + lq) * 64 + c) = __floats2half2_rn(ox, oy);
        float oz = fmaxf(acc2[j][2] + bx, 0.f);
        float ow = fmaxf(acc2[j][3] + by, 0.f);
        *(__half2*)(out + (row0 + lq + 8) * 64 + c) = __floats2half2_rn(oz, ow);
    }
}

// ---------------- pooling: out[b, c, t] (max) and [b, 64+c, t] (mean) --------
// Vectorized: thread owns half2 channel pair c2=tid&31; 8 row-groups.
template <bool FIRST>
__global__ void __launch_bounds__(256) pool_all_kernel(const __half* __restrict__ h,
                                                       float* __restrict__ out) {
    int b = blockIdx.x, t = blockIdx.y;
    int tid = threadIdx.x;
    int c2 = tid & 31, g = tid >> 5;  // 8 groups
    const __half2* hp = (const __half2*)(h + ((size_t)b * NPG * 8 + t) * 64) + c2;
    float2 mx = make_float2(-1e30f, -1e30f);
    float2 sm = make_float2(0.f, 0.f);
    for (int i = g; i < NPG; i += 8) {
        float2 f = __half22float2(hp[(size_t)i * 256]);
        mx.x = fmaxf(mx.x, f.x); mx.y = fmaxf(mx.y, f.y);
        sm.x += f.x; sm.y += f.y;
    }
    __shared__ float2 smx[8][32], ssm[8][32];
    smx[g][c2] = mx; ssm[g][c2] = sm;
    __syncthreads();
    if (tid < 32) {
        float2 m = smx[0][tid], s = ssm[0][tid];
#pragma unroll
        for (int k = 1; k < 8; k++) {
            m.x = fmaxf(m.x, smx[k][tid].x); m.y = fmaxf(m.y, smx[k][tid].y);
            s.x += ssm[k][tid].x;            s.y += ssm[k][tid].y;
        }
        s.x *= (1.f / (float)NPG); s.y *= (1.f / (float)NPG);
        int c0 = 2 * tid;
        float* ob = out + b * 1024;
        if (FIRST) {
            ob[c0 * 8 + t]        = m.x; ob[(c0 + 1) * 8 + t]  = m.y;
            ob[(64 + c0) * 8 + t] = s.x; ob[(65 + c0) * 8 + t] = s.y;
        } else {
            ob[c0 * 8 + t]        += m.x; ob[(c0 + 1) * 8 + t]  += m.y;
            ob[(64 + c0) * 8 + t] += s.x; ob[(65 + c0) * 8 + t] += s.y;
        }
    }
}

// ---------------- launch -----------------------------------------------------
extern "C" void kernel_launch(void* const* d_in, const int* in_sizes, int n_in,
                              void* d_out, int out_size) {
    const float* x  = (const float*)d_in[0];
    const int*   ei = (const int*)d_in[1];     // int32 [2, E]
    const float* W1 = (const float*)d_in[3];
    const float* b1 = (const float*)d_in[4];
    const float* W2 = (const float*)d_in[5];
    const float* b2 = (const float*)d_in[6];
    const float* W3 = (const float*)d_in[7];
    const float* b3 = (const float*)d_in[8];
    float* out = (float*)d_out;

    __half *xh, *hA, *hB;
    uint2 *wf1, *wf2, *wf3;
    cudaGetSymbolAddress((void**)&xh,  g_xh);
    cudaGetSymbolAddress((void**)&hA,  g_hA);
    cudaGetSymbolAddress((void**)&hB,  g_hB);
    cudaGetSymbolAddress((void**)&wf1, g_Wf1);
    cudaGetSymbolAddress((void**)&wf2, g_Wf2);
    cudaGetSymbolAddress((void**)&wf3, g_Wf3);

    // setup (deg/cnt zero: module load on call 1, fused<32> thereafter)
    setup_all_kernel<<<(N_NODES * C_IN + 255) / 256, 256>>>(x, ei, W1, W2, W3);
    scan_part_kernel<<<SCAN_NBLK, 256>>>();
    scan_apply_kernel<<<(N_NODES + 1023) / 1024, 1024>>>();
    fill_csr_kernel<<<(N_EDGES + 255) / 256, 256>>>(ei);

    const int FUSE_GRID = N_NODES / 16;   // 3125 blocks, 16 nodes, 8 warps
    dim3 pool_grid(NB, NT);

    // layer 1: xh -> hA  (+ deg/cnt cleanup for next replay)
    fused_agg_gemm_kernel<32, true><<<FUSE_GRID, 256>>>((const uint4*)xh, wf1, b1, hA);
    pool_all_kernel<true><<<pool_grid, 256>>>(hA, out);
    // layer 2: hA -> hB
    fused_agg_gemm_kernel<64, false><<<FUSE_GRID, 256>>>((const uint4*)hA, wf2, b2, hB);
    pool_all_kernel<false><<<pool_grid, 256>>>(hB, out);
    // layer 3: hB -> hA
    fused_agg_gemm_kernel<64, false><<<FUSE_GRID, 256>>>((const uint4*)hB, wf3, b3, hA);
    pool_all_kernel<false><<<pool_grid, 256>>>(hA, out);
}